// round 2
// baseline (speedup 1.0000x reference)
#include <cuda_runtime.h>

// Problem: src [4,2048,128] f32, tgt [4,2048,128] f32
// out [4,2048,2048,2] f32: out[b,n,m,0]=cosine, out[b,n,m,1]=1/(1+dist)
// cosine = dot(s,t) * (1/max(|s|,eps)) * (1/max(|t|,eps))
// dist   = sqrt(max(|s|^2 + |t|^2 - 2 dot, 0))

#define BT 4
#define NN 2048
#define CC 128
#define ROWS (BT * NN)   // 8192 rows per tensor

#define BM 128
#define BN 128
#define BK 8
#define PAD 132          // smem row pad to kill STS bank conflicts

// Scratch: per-row squared norms and inverse norms (allocation-free rule: __device__ globals)
__device__ float g_ssq[ROWS];
__device__ float g_tsq[ROWS];
__device__ float g_rs[ROWS];
__device__ float g_rt[ROWS];

// ---------------------------------------------------------------------------
// Kernel A: row norms. One warp per row (128 floats = 32 lanes x float4).
// ---------------------------------------------------------------------------
__global__ void norms_kernel(const float* __restrict__ src,
                             const float* __restrict__ tgt) {
    int gw   = (blockIdx.x * blockDim.x + threadIdx.x) >> 5;  // global warp = row
    int lane = threadIdx.x & 31;
    if (gw >= ROWS) return;
    bool is_t = (blockIdx.y != 0);
    const float* p = (is_t ? tgt : src) + (size_t)gw * CC + lane * 4;
    float4 v = *(const float4*)p;
    float s = v.x * v.x + v.y * v.y + v.z * v.z + v.w * v.w;
#pragma unroll
    for (int o = 16; o; o >>= 1) s += __shfl_xor_sync(0xffffffffu, s, o);
    if (lane == 0) {
        float r = 1.0f / fmaxf(sqrtf(s), 1e-12f);
        if (is_t) { g_tsq[gw] = s; g_rt[gw] = r; }
        else      { g_ssq[gw] = s; g_rs[gw] = r; }
    }
}

// ---------------------------------------------------------------------------
// Packed f32x2 helpers (sm_103a FFMA2 — 2 fp32 FMAs per instruction)
// ---------------------------------------------------------------------------
union F2U { float2 f; unsigned long long u; };

__device__ __forceinline__ unsigned long long pack2(float lo, float hi) {
    F2U t; t.f.x = lo; t.f.y = hi; return t.u;
}
__device__ __forceinline__ void fma2(unsigned long long& d,
                                     unsigned long long a,
                                     unsigned long long b) {
    asm("fma.rn.f32x2 %0, %1, %2, %0;" : "+l"(d) : "l"(a), "l"(b));
}

// ---------------------------------------------------------------------------
// Kernel B: 128x128x128 tile GEMM + fused similarity epilogue.
// 256 threads = 16x16, each thread an 8x8 microtile (4+4 split in each dim),
// accumulators held as 8x4 f32x2 pairs.
// ---------------------------------------------------------------------------
__global__ __launch_bounds__(256, 2)
void sim_gemm(const float* __restrict__ S, const float* __restrict__ T,
              float* __restrict__ out) {
    __shared__ float As[BK][PAD];
    __shared__ float Bs[BK][PAD];

    const int b  = blockIdx.z;
    const int bi = blockIdx.y * BM;
    const int bj = blockIdx.x * BN;
    const int tid = threadIdx.x;
    const int tx = tid & 15;          // 0..15 -> j
    const int ty = tid >> 4;          // 0..15 -> i

    const float* Sb = S + (size_t)b * NN * CC;
    const float* Tb = T + (size_t)b * NN * CC;

    // global tile loads: each thread one float4 of A and one of B per k-chunk
    const int lrow = tid >> 1;        // 0..127
    const int lk   = (tid & 1) * 4;   // 0 or 4
    const float* gA = Sb + (size_t)(bi + lrow) * CC + lk;
    const float* gB = Tb + (size_t)(bj + lrow) * CC + lk;

    unsigned long long acc[8][4];
#pragma unroll
    for (int i = 0; i < 8; i++)
#pragma unroll
        for (int j = 0; j < 4; j++) acc[i][j] = 0ULL;

    float4 fa = *(const float4*)gA;
    float4 fb = *(const float4*)gB;

#pragma unroll 1
    for (int kt = 0; kt < CC / BK; kt++) {
        // scatter current k-chunk to smem (transposed: [k][row])
        As[lk + 0][lrow] = fa.x; As[lk + 1][lrow] = fa.y;
        As[lk + 2][lrow] = fa.z; As[lk + 3][lrow] = fa.w;
        Bs[lk + 0][lrow] = fb.x; Bs[lk + 1][lrow] = fb.y;
        Bs[lk + 2][lrow] = fb.z; Bs[lk + 3][lrow] = fb.w;
        __syncthreads();

        // prefetch next chunk while computing this one
        if (kt + 1 < CC / BK) {
            fa = *(const float4*)(gA + (kt + 1) * BK);
            fb = *(const float4*)(gB + (kt + 1) * BK);
        }

#pragma unroll
        for (int k = 0; k < BK; k++) {
            float4 a0 = *(const float4*)&As[k][ty * 4];
            float4 a1 = *(const float4*)&As[k][64 + ty * 4];
            float4 b0 = *(const float4*)&Bs[k][tx * 4];
            float4 b1 = *(const float4*)&Bs[k][64 + tx * 4];
            unsigned long long bp[4] = {
                pack2(b0.x, b0.y), pack2(b0.z, b0.w),
                pack2(b1.x, b1.y), pack2(b1.z, b1.w)
            };
            float av[8] = {a0.x, a0.y, a0.z, a0.w, a1.x, a1.y, a1.z, a1.w};
#pragma unroll
            for (int i = 0; i < 8; i++) {
                unsigned long long ap = pack2(av[i], av[i]);
                fma2(acc[i][0], ap, bp[0]);
                fma2(acc[i][1], ap, bp[1]);
                fma2(acc[i][2], ap, bp[2]);
                fma2(acc[i][3], ap, bp[3]);
            }
        }
        __syncthreads();
    }

    // -------- fused epilogue --------
    float ssq[8], rs[8];
    int rowi[8];
#pragma unroll
    for (int i = 0; i < 8; i++) {
        int r = (i < 4) ? (ty * 4 + i) : (64 + ty * 4 + (i - 4));
        rowi[i] = bi + r;
        ssq[i] = g_ssq[b * NN + rowi[i]];
        rs[i]  = g_rs [b * NN + rowi[i]];
    }
    float tsq[8], rt[8];
    int colj[8];
#pragma unroll
    for (int j = 0; j < 8; j++) {
        int c = (j < 4) ? (tx * 4 + j) : (64 + tx * 4 + (j - 4));
        colj[j] = bj + c;
        tsq[j] = g_tsq[b * NN + colj[j]];
        rt[j]  = g_rt [b * NN + colj[j]];
    }

#pragma unroll
    for (int i = 0; i < 8; i++) {
        float* rowbase = out + ((size_t)(b * NN + rowi[i]) * NN) * 2;
#pragma unroll
        for (int jp = 0; jp < 4; jp++) {
            // pair jp covers columns j0 = 2*jp (in the 0..7 microtile index space)
            int j0 = jp * 2;
            F2U u; u.u = acc[i][jp];
            float dot0 = u.f.x, dot1 = u.f.y;

            float cos0 = dot0 * rs[i] * rt[j0];
            float cos1 = dot1 * rs[i] * rt[j0 + 1];
            float d0 = fmaxf(ssq[i] + tsq[j0]     - 2.0f * dot0, 0.0f);
            float d1 = fmaxf(ssq[i] + tsq[j0 + 1] - 2.0f * dot1, 0.0f);
            float fd0 = 1.0f / (1.0f + sqrtf(d0));
            float fd1 = 1.0f / (1.0f + sqrtf(d1));

            // cols are consecutive (even start) -> one 16B store of {cos,fd,cos,fd}
            float4 o = make_float4(cos0, fd0, cos1, fd1);
            *(float4*)(rowbase + (size_t)colj[j0] * 2) = o;
        }
    }
}

// ---------------------------------------------------------------------------
extern "C" void kernel_launch(void* const* d_in, const int* in_sizes, int n_in,
                              void* d_out, int out_size) {
    const float* src = (const float*)d_in[0];
    const float* tgt = (const float*)d_in[1];
    float* out = (float*)d_out;
    (void)in_sizes; (void)n_in; (void)out_size;

    // 8192 rows per tensor, 8 warps/block -> 1024 blocks; y selects src/tgt
    norms_kernel<<<dim3(1024, 2, 1), 256>>>(src, tgt);
    // 2048/128 = 16 tiles per dim, 4 batches
    sim_gemm<<<dim3(16, 16, 4), 256>>>(src, tgt, out);
}

// round 5
// speedup vs baseline: 1.2721x; 1.2721x over previous
#include <cuda_runtime.h>
#include <cuda_fp16.h>
#include <cstdint>

// out[b,n,m,0]=cos(src_n,tgt_m), out[b,n,m,1]=1/(1+||src_n-tgt_m||)
// dot via split-fp16 mma.sync (hi*hi + hi*lo + lo*hi), fp32 accumulate.
// GEMM C[n][m]: A = src (row-major m16k16 frags), B = tgt (col-major k16n8 frags).

#define NN 2048
#define CC 128
#define ROWSZ (4 * NN)

// fp16 split scratch + norms (allocation-free: __device__ globals)
__device__ __half g_hiS[ROWSZ * CC];
__device__ __half g_loS[ROWSZ * CC];
__device__ __half g_hiT[ROWSZ * CC];
__device__ __half g_loT[ROWSZ * CC];
__device__ float2 g_nS[ROWSZ];   // {|s|^2, 1/max(|s|,eps)}
__device__ float2 g_nT[ROWSZ];

// ---------------------------------------------------------------------------
// prep: fp32 -> (hi, lo) fp16 split + fused row norms. One warp per row.
// ---------------------------------------------------------------------------
__global__ void prep(const float* __restrict__ S, const float* __restrict__ T) {
    int gw = (blockIdx.x * blockDim.x + threadIdx.x) >> 5;
    int lane = threadIdx.x & 31;
    if (gw >= ROWSZ) return;
    bool ist = (blockIdx.y != 0);
    const float* p = (ist ? T : S) + (size_t)gw * CC + lane * 4;
    float4 v = *(const float4*)p;
    float sq = v.x * v.x + v.y * v.y + v.z * v.z + v.w * v.w;
#pragma unroll
    for (int o = 16; o; o >>= 1) sq += __shfl_xor_sync(0xffffffffu, sq, o);

    __half2 h01 = __floats2half2_rn(v.x, v.y);
    __half2 h23 = __floats2half2_rn(v.z, v.w);
    float2 f01 = __half22float2(h01);
    float2 f23 = __half22float2(h23);
    __half2 l01 = __floats2half2_rn(v.x - f01.x, v.y - f01.y);
    __half2 l23 = __floats2half2_rn(v.z - f23.x, v.w - f23.y);

    size_t off = (size_t)gw * CC + lane * 4;
    __half* hi = ist ? g_hiT : g_hiS;
    __half* lo = ist ? g_loT : g_loS;
    *(uint2*)(hi + off) = make_uint2(*(uint32_t*)&h01, *(uint32_t*)&h23);
    *(uint2*)(lo + off) = make_uint2(*(uint32_t*)&l01, *(uint32_t*)&l23);
    if (lane == 0) {
        float2 nv;
        nv.x = sq;
        nv.y = 1.0f / fmaxf(sqrtf(sq), 1e-12f);
        (ist ? g_nT : g_nS)[gw] = nv;
    }
}

// ---------------------------------------------------------------------------
// helpers
// ---------------------------------------------------------------------------
__device__ __forceinline__ uint32_t s2u(const void* p) {
    uint32_t a;
    asm("{ .reg .u64 t; cvta.to.shared.u64 t, %1; cvt.u32.u64 %0, t; }" : "=r"(a) : "l"(p));
    return a;
}
// tile layout: 128 rows x 32 halfs (4x 16B k-groups). Conflict-free for both
// cp.async stores (2 rows x 4 kg per 8-lane phase) and ldmatrix reads
// (8 rows, fixed kg).  slot = (row&7) ^ kg ^ ((row&1)<<2)
__device__ __forceinline__ uint32_t toff(int row, int kg) {
    return (uint32_t)((kg << 11) + ((row >> 3) << 7) +
                      (((((row & 7) ^ kg) ^ ((row & 1) << 2))) << 4));
}
__device__ __forceinline__ void cpasync16(uint32_t s, const void* g) {
    asm volatile("cp.async.cg.shared.global [%0], [%1], 16;" :: "r"(s), "l"(g) : "memory");
}
template <int N>
__device__ __forceinline__ void cpwait() {
    asm volatile("cp.async.wait_group %0;" :: "n"(N) : "memory");
}
__device__ __forceinline__ void ldm4(uint32_t& r0, uint32_t& r1, uint32_t& r2,
                                     uint32_t& r3, uint32_t a) {
    asm volatile("ldmatrix.sync.aligned.m8n8.x4.shared.b16 {%0,%1,%2,%3}, [%4];"
                 : "=r"(r0), "=r"(r1), "=r"(r2), "=r"(r3) : "r"(a));
}
__device__ __forceinline__ void mma16816(float* c, const uint32_t* a, const uint32_t* b) {
    asm volatile(
        "mma.sync.aligned.m16n8k16.row.col.f32.f16.f16.f32 "
        "{%0,%1,%2,%3}, {%4,%5,%6,%7}, {%8,%9}, {%0,%1,%2,%3};"
        : "+f"(c[0]), "+f"(c[1]), "+f"(c[2]), "+f"(c[3])
        : "r"(a[0]), "r"(a[1]), "r"(a[2]), "r"(a[3]), "r"(b[0]), "r"(b[1]));
}
__device__ __forceinline__ float sqrt_ap(float x) { float r; asm("sqrt.approx.f32 %0,%1;" : "=f"(r) : "f"(x)); return r; }
__device__ __forceinline__ float rcp_ap(float x)  { float r; asm("rcp.approx.f32 %0,%1;"  : "=f"(r) : "f"(x)); return r; }

// ---------------------------------------------------------------------------
// GEMM + fused similarity epilogue.
// CTA: 128 n-rows x 128 m-cols.  8 warps = 2(n) x 4(m), warp tile 64x32.
// Virtual K = 384 (3 passes x 128), chunk = 32 halfs, 12 chunks, 3-stage pipe.
// ---------------------------------------------------------------------------
__global__ __launch_bounds__(256, 2)
void simgemm(float* __restrict__ out) {
    __shared__ __align__(1024) char sm[49152];   // 3 stages x (A 8K + B 8K)
    uint32_t sb = s2u(sm);
    const int tid = threadIdx.x, lane = tid & 31, w = tid >> 5;
    const int wm = w & 1, wn = w >> 1;
    const int b = blockIdx.z, bm = blockIdx.x, bn = blockIdx.y;
    const int aRow0 = b * NN + bn * 128;   // src rows (C rows, n)
    const int bRow0 = b * NN + bm * 128;   // tgt rows (C cols, m)

    float acc[4][4][4];
#pragma unroll
    for (int i = 0; i < 4; i++)
#pragma unroll
        for (int j = 0; j < 4; j++)
#pragma unroll
            for (int k = 0; k < 4; k++) acc[i][j][k] = 0.0f;

    // per-thread ldmatrix smem offsets
    uint32_t aoff[4][2], boff[2][2];
    {
        int ar = (lane & 7) + ((lane >> 3) & 1) * 8;  // row within 16-block
        int akg = lane >> 4;                           // kg half
#pragma unroll
        for (int mi = 0; mi < 4; mi++)
#pragma unroll
            for (int kk = 0; kk < 2; kk++)
                aoff[mi][kk] = toff(wm * 64 + mi * 16 + ar, kk * 2 + akg);
        int br = (lane & 7) + (lane >> 4) * 8;         // row within 16 (2 n8 blocks)
        int bkg = (lane >> 3) & 1;
#pragma unroll
        for (int nip = 0; nip < 2; nip++)
#pragma unroll
            for (int kk = 0; kk < 2; kk++)
                boff[nip][kk] = toff(wn * 32 + nip * 16 + br, kk * 2 + bkg);
    }

    // chunk c: pass p=c>>2 selects arrays, kq=c&3 selects 32-half K slice
    auto issue = [&](int c, int stage) {
        int p = c >> 2, kq = c & 3;
        const __half* ga = (p == 2 ? g_loS : g_hiS) + (size_t)aRow0 * CC + kq * 32;
        const __half* gb = (p == 1 ? g_loT : g_hiT) + (size_t)bRow0 * CC + kq * 32;
        uint32_t sA = sb + stage * 16384;
        uint32_t sB = sA + 8192;
#pragma unroll
        for (int j = 0; j < 2; j++) {
            int g = tid + j * 256;
            int row = g >> 2, kg = g & 3;
            uint32_t o = toff(row, kg);
            cpasync16(sA + o, ga + (size_t)row * CC + kg * 8);
            cpasync16(sB + o, gb + (size_t)row * CC + kg * 8);
        }
        asm volatile("cp.async.commit_group;" ::: "memory");
    };

    auto compute = [&](int stage) {
        uint32_t sA = sb + stage * 16384;
        uint32_t sB = sA + 8192;
#pragma unroll
        for (int kk = 0; kk < 2; kk++) {
            uint32_t a[4][4];
#pragma unroll
            for (int mi = 0; mi < 4; mi++)
                ldm4(a[mi][0], a[mi][1], a[mi][2], a[mi][3], sA + aoff[mi][kk]);
            uint32_t bf[4][2];
#pragma unroll
            for (int nip = 0; nip < 2; nip++)
                ldm4(bf[nip * 2][0], bf[nip * 2][1], bf[nip * 2 + 1][0],
                     bf[nip * 2 + 1][1], sB + boff[nip][kk]);
#pragma unroll
            for (int mi = 0; mi < 4; mi++)
#pragma unroll
                for (int ni = 0; ni < 4; ni++)
                    mma16816(acc[mi][ni], a[mi], bf[ni]);
        }
    };

    issue(0, 0); issue(1, 1); issue(2, 2);
#pragma unroll
    for (int c = 0; c < 12; c++) {
        if (c <= 9)      cpwait<2>();
        else if (c == 10) cpwait<1>();
        else              cpwait<0>();
        __syncthreads();
        compute(c % 3);
        __syncthreads();
        if (c + 3 < 12) issue(c + 3, c % 3);
    }

    // ---- epilogue ----
    const int q = lane >> 2;          // row group 0..7
    const int mp = (lane & 3) * 2;    // col pair base
#pragma unroll
    for (int mi = 0; mi < 4; mi++) {
        int n0 = bn * 128 + wm * 64 + mi * 16 + q;
        float2 ns0 = g_nS[b * NN + n0];
        float2 ns1 = g_nS[b * NN + n0 + 8];
        float* r0 = out + (((size_t)(b * NN + n0)) * NN) * 2;
        float* r1 = out + (((size_t)(b * NN + n0 + 8)) * NN) * 2;
#pragma unroll
        for (int ni = 0; ni < 4; ni++) {
            int m0 = bm * 128 + wn * 32 + ni * 8 + mp;
            float2 nt0 = g_nT[b * NN + m0];
            float2 nt1 = g_nT[b * NN + m0 + 1];
            const float* cc = acc[mi][ni];

            float cs00 = cc[0] * ns0.y * nt0.y;
            float cs01 = cc[1] * ns0.y * nt1.y;
            float cs10 = cc[2] * ns1.y * nt0.y;
            float cs11 = cc[3] * ns1.y * nt1.y;
            float fd00 = rcp_ap(1.0f + sqrt_ap(fmaxf(ns0.x + nt0.x - 2.0f * cc[0], 0.0f)));
            float fd01 = rcp_ap(1.0f + sqrt_ap(fmaxf(ns0.x + nt1.x - 2.0f * cc[1], 0.0f)));
            float fd10 = rcp_ap(1.0f + sqrt_ap(fmaxf(ns1.x + nt0.x - 2.0f * cc[2], 0.0f)));
            float fd11 = rcp_ap(1.0f + sqrt_ap(fmaxf(ns1.x + nt1.x - 2.0f * cc[3], 0.0f)));

            *(float4*)(r0 + (size_t)m0 * 2) = make_float4(cs00, fd00, cs01, fd01);
            *(float4*)(r1 + (size_t)m0 * 2) = make_float4(cs10, fd10, cs11, fd11);
        }
    }
}

// ---------------------------------------------------------------------------
extern "C" void kernel_launch(void* const* d_in, const int* in_sizes, int n_in,
                              void* d_out, int out_size) {
    const float* src = (const float*)d_in[0];
    const float* tgt = (const float*)d_in[1];
    float* out = (float*)d_out;
    (void)in_sizes; (void)n_in; (void)out_size;

    prep<<<dim3(1024, 2, 1), 256>>>(src, tgt);
    simgemm<<<dim3(16, 16, 4), 256>>>(out);
}

// round 6
// speedup vs baseline: 1.4654x; 1.1520x over previous
#include <cuda_runtime.h>
#include <cuda_fp16.h>
#include <cstdint>

// out[b,n,m,0]=cos(src_n,tgt_m), out[b,n,m,1]=1/(1+||src_n-tgt_m||)
// dot via split-fp16 mma.sync: hi*hi + hi*lo + lo*hi, fp32 accumulate.
// All 3 passes computed from ONE smem residency per K-slice (4 tiles/slice).

#define NN 2048
#define CC 128
#define ROWSZ (4 * NN)

__device__ __half g_hiS[ROWSZ * CC];
__device__ __half g_loS[ROWSZ * CC];
__device__ __half g_hiT[ROWSZ * CC];
__device__ __half g_loT[ROWSZ * CC];
__device__ float2 g_nS[ROWSZ];   // {|s|^2, 1/max(|s|,eps)}
__device__ float2 g_nT[ROWSZ];

// ---------------------------------------------------------------------------
// prep: fp32 -> (hi, lo) fp16 split + fused row norms. One warp per row.
// ---------------------------------------------------------------------------
__global__ void prep(const float* __restrict__ S, const float* __restrict__ T) {
    int gw = (blockIdx.x * blockDim.x + threadIdx.x) >> 5;
    int lane = threadIdx.x & 31;
    if (gw >= ROWSZ) return;
    bool ist = (blockIdx.y != 0);
    const float* p = (ist ? T : S) + (size_t)gw * CC + lane * 4;
    float4 v = *(const float4*)p;
    float sq = v.x * v.x + v.y * v.y + v.z * v.z + v.w * v.w;
#pragma unroll
    for (int o = 16; o; o >>= 1) sq += __shfl_xor_sync(0xffffffffu, sq, o);

    __half2 h01 = __floats2half2_rn(v.x, v.y);
    __half2 h23 = __floats2half2_rn(v.z, v.w);
    float2 f01 = __half22float2(h01);
    float2 f23 = __half22float2(h23);
    __half2 l01 = __floats2half2_rn(v.x - f01.x, v.y - f01.y);
    __half2 l23 = __floats2half2_rn(v.z - f23.x, v.w - f23.y);

    size_t off = (size_t)gw * CC + lane * 4;
    __half* hi = ist ? g_hiT : g_hiS;
    __half* lo = ist ? g_loT : g_loS;
    *(uint2*)(hi + off) = make_uint2(*(uint32_t*)&h01, *(uint32_t*)&h23);
    *(uint2*)(lo + off) = make_uint2(*(uint32_t*)&l01, *(uint32_t*)&l23);
    if (lane == 0) {
        float2 nv;
        nv.x = sq;
        nv.y = 1.0f / fmaxf(sqrtf(sq), 1e-12f);
        (ist ? g_nT : g_nS)[gw] = nv;
    }
}

// ---------------------------------------------------------------------------
__device__ __forceinline__ uint32_t s2u(const void* p) {
    uint32_t a;
    asm("{ .reg .u64 t; cvta.to.shared.u64 t, %1; cvt.u32.u64 %0, t; }" : "=r"(a) : "l"(p));
    return a;
}
// 128 rows x 32 halfs tile, 16B granules. slot = (row&7)^kg^((row&1)<<2):
// conflict-free for cp.async stores (2 rows x 4 kg / phase) and ldmatrix reads.
__device__ __forceinline__ uint32_t toff(int row, int kg) {
    return (uint32_t)((kg << 11) + ((row >> 3) << 7) +
                      (((((row & 7) ^ kg) ^ ((row & 1) << 2))) << 4));
}
__device__ __forceinline__ void cpasync16(uint32_t s, const void* g) {
    asm volatile("cp.async.cg.shared.global [%0], [%1], 16;" :: "r"(s), "l"(g) : "memory");
}
template <int N>
__device__ __forceinline__ void cpwait() {
    asm volatile("cp.async.wait_group %0;" :: "n"(N) : "memory");
}
__device__ __forceinline__ void ldm4(uint32_t& r0, uint32_t& r1, uint32_t& r2,
                                     uint32_t& r3, uint32_t a) {
    asm volatile("ldmatrix.sync.aligned.m8n8.x4.shared.b16 {%0,%1,%2,%3}, [%4];"
                 : "=r"(r0), "=r"(r1), "=r"(r2), "=r"(r3) : "r"(a));
}
__device__ __forceinline__ void mma16816(float* c, const uint32_t* a, const uint32_t* b) {
    asm volatile(
        "mma.sync.aligned.m16n8k16.row.col.f32.f16.f16.f32 "
        "{%0,%1,%2,%3}, {%4,%5,%6,%7}, {%8,%9}, {%0,%1,%2,%3};"
        : "+f"(c[0]), "+f"(c[1]), "+f"(c[2]), "+f"(c[3])
        : "r"(a[0]), "r"(a[1]), "r"(a[2]), "r"(a[3]), "r"(b[0]), "r"(b[1]));
}
__device__ __forceinline__ float sqrt_ap(float x) { float r; asm("sqrt.approx.f32 %0,%1;" : "=f"(r) : "f"(x)); return r; }
__device__ __forceinline__ float rcp_ap(float x)  { float r; asm("rcp.approx.f32 %0,%1;"  : "=f"(r) : "f"(x)); return r; }

// ---------------------------------------------------------------------------
// GEMM + fused epilogue. CTA 128(n) x 128(m), 8 warps 2(n) x 4(m), warp 64x32.
// K = 128 in 4 slices of 32. Per slice: one residency {hiA, loA, hiB, loB},
// three mma groups. 2-stage cp.async pipeline, 64KB dynamic smem, 2 CTA/SM.
// ---------------------------------------------------------------------------
#define STG_BYTES 32768   // 4 tiles x 8KB

__global__ __launch_bounds__(256, 2)
void simgemm(float* __restrict__ out) {
    extern __shared__ __align__(1024) char sm[];
    uint32_t sb = s2u(sm);
    const int tid = threadIdx.x, lane = tid & 31, w = tid >> 5;
    const int wm = w & 1, wn = w >> 1;
    const int b = blockIdx.z, bm = blockIdx.x, bn = blockIdx.y;
    const int aRow0 = b * NN + bn * 128;   // src rows (C rows, n)
    const int bRow0 = b * NN + bm * 128;   // tgt rows (C cols, m)

    float acc[4][4][4];
#pragma unroll
    for (int i = 0; i < 4; i++)
#pragma unroll
        for (int j = 0; j < 4; j++)
#pragma unroll
            for (int k = 0; k < 4; k++) acc[i][j][k] = 0.0f;

    // ldmatrix per-thread offsets (within one 8KB tile)
    uint32_t aoff[4][2], boff[2][2];
    {
        int ar = (lane & 7) + ((lane >> 3) & 1) * 8;
        int akg = lane >> 4;
#pragma unroll
        for (int mi = 0; mi < 4; mi++)
#pragma unroll
            for (int kk = 0; kk < 2; kk++)
                aoff[mi][kk] = toff(wm * 64 + mi * 16 + ar, kk * 2 + akg);
        int br = (lane & 7) + (lane >> 4) * 8;
        int bkg = (lane >> 3) & 1;
#pragma unroll
        for (int nip = 0; nip < 2; nip++)
#pragma unroll
            for (int kk = 0; kk < 2; kk++)
                boff[nip][kk] = toff(wn * 32 + nip * 16 + br, kk * 2 + bkg);
    }

    // issue slice s into stage: 4 tiles (hiA, loA, hiB, loB), 8 cp.async/thread
    auto issue = [&](int s, int stage) {
        const __half* gah = g_hiS + (size_t)aRow0 * CC + s * 32;
        const __half* gal = g_loS + (size_t)aRow0 * CC + s * 32;
        const __half* gbh = g_hiT + (size_t)bRow0 * CC + s * 32;
        const __half* gbl = g_loT + (size_t)bRow0 * CC + s * 32;
        uint32_t st = sb + stage * STG_BYTES;
#pragma unroll
        for (int j = 0; j < 2; j++) {
            int g = tid + j * 256;
            int row = g >> 2, kg = g & 3;
            uint32_t o = toff(row, kg);
            size_t go = (size_t)row * CC + kg * 8;
            cpasync16(st + o,         gah + go);
            cpasync16(st + 8192 + o,  gal + go);
            cpasync16(st + 16384 + o, gbh + go);
            cpasync16(st + 24576 + o, gbl + go);
        }
        asm volatile("cp.async.commit_group;" ::: "memory");
    };

    auto compute = [&](int stage) {
        uint32_t st = sb + stage * STG_BYTES;
#pragma unroll
        for (int kk = 0; kk < 2; kk++) {
            uint32_t bh[4][2], bl[4][2];
#pragma unroll
            for (int nip = 0; nip < 2; nip++) {
                ldm4(bh[nip * 2][0], bh[nip * 2][1], bh[nip * 2 + 1][0],
                     bh[nip * 2 + 1][1], st + 16384 + boff[nip][kk]);
                ldm4(bl[nip * 2][0], bl[nip * 2][1], bl[nip * 2 + 1][0],
                     bl[nip * 2 + 1][1], st + 24576 + boff[nip][kk]);
            }
            uint32_t a[4][4];
            // hiA: hi*hi and hi*lo
#pragma unroll
            for (int mi = 0; mi < 4; mi++)
                ldm4(a[mi][0], a[mi][1], a[mi][2], a[mi][3], st + aoff[mi][kk]);
#pragma unroll
            for (int mi = 0; mi < 4; mi++)
#pragma unroll
                for (int ni = 0; ni < 4; ni++)
                    mma16816(acc[mi][ni], a[mi], bh[ni]);
#pragma unroll
            for (int mi = 0; mi < 4; mi++)
#pragma unroll
                for (int ni = 0; ni < 4; ni++)
                    mma16816(acc[mi][ni], a[mi], bl[ni]);
            // loA: lo*hi (reuse a regs)
#pragma unroll
            for (int mi = 0; mi < 4; mi++)
                ldm4(a[mi][0], a[mi][1], a[mi][2], a[mi][3], st + 8192 + aoff[mi][kk]);
#pragma unroll
            for (int mi = 0; mi < 4; mi++)
#pragma unroll
                for (int ni = 0; ni < 4; ni++)
                    mma16816(acc[mi][ni], a[mi], bh[ni]);
        }
    };

    issue(0, 0);
    issue(1, 1);
#pragma unroll
    for (int c = 0; c < 4; c++) {
        if (c < 3) cpwait<1>(); else cpwait<0>();
        __syncthreads();
        compute(c & 1);
        __syncthreads();
        if (c + 2 < 4) issue(c + 2, c & 1);
    }

    // ---- epilogue ----
    const int q = lane >> 2;
    const int mp = (lane & 3) * 2;
#pragma unroll
    for (int mi = 0; mi < 4; mi++) {
        int n0 = bn * 128 + wm * 64 + mi * 16 + q;
        float2 ns0 = g_nS[b * NN + n0];
        float2 ns1 = g_nS[b * NN + n0 + 8];
        float* r0 = out + (((size_t)(b * NN + n0)) * NN) * 2;
        float* r1 = out + (((size_t)(b * NN + n0 + 8)) * NN) * 2;
#pragma unroll
        for (int ni = 0; ni < 4; ni++) {
            int m0 = bm * 128 + wn * 32 + ni * 8 + mp;
            float2 nt0 = g_nT[b * NN + m0];
            float2 nt1 = g_nT[b * NN + m0 + 1];
            const float* cc = acc[mi][ni];

            float cs00 = cc[0] * ns0.y * nt0.y;
            float cs01 = cc[1] * ns0.y * nt1.y;
            float cs10 = cc[2] * ns1.y * nt0.y;
            float cs11 = cc[3] * ns1.y * nt1.y;
            float fd00 = rcp_ap(1.0f + sqrt_ap(fmaxf(ns0.x + nt0.x - 2.0f * cc[0], 0.0f)));
            float fd01 = rcp_ap(1.0f + sqrt_ap(fmaxf(ns0.x + nt1.x - 2.0f * cc[1], 0.0f)));
            float fd10 = rcp_ap(1.0f + sqrt_ap(fmaxf(ns1.x + nt0.x - 2.0f * cc[2], 0.0f)));
            float fd11 = rcp_ap(1.0f + sqrt_ap(fmaxf(ns1.x + nt1.x - 2.0f * cc[3], 0.0f)));

            *(float4*)(r0 + (size_t)m0 * 2) = make_float4(cs00, fd00, cs01, fd01);
            *(float4*)(r1 + (size_t)m0 * 2) = make_float4(cs10, fd10, cs11, fd11);
        }
    }
}

// ---------------------------------------------------------------------------
extern "C" void kernel_launch(void* const* d_in, const int* in_sizes, int n_in,
                              void* d_out, int out_size) {
    const float* src = (const float*)d_in[0];
    const float* tgt = (const float*)d_in[1];
    float* out = (float*)d_out;
    (void)in_sizes; (void)n_in; (void)out_size;

    cudaFuncSetAttribute(simgemm, cudaFuncAttributeMaxDynamicSharedMemorySize,
                         2 * STG_BYTES);
    prep<<<dim3(1024, 2, 1), 256>>>(src, tgt);
    simgemm<<<dim3(16, 16, 4), 256, 2 * STG_BYTES>>>(out);
}